// round 2
// baseline (speedup 1.0000x reference)
#include <cuda_runtime.h>
#include <stdint.h>
#include <math.h>

// Problem constants
#define NIMG 256          // B*F = 16*16
#define HH   224
#define WW   224
#define NPIX (HH*WW)      // 50176
#define NOFF 4

// Scratch (static device arrays: no allocation allowed)
__device__ unsigned char d_g[(size_t)NIMG * NPIX];   // 12.8 MB grayscale
__device__ float d_std[NIMG];
__device__ float d_feat[NIMG * NOFF * 4];            // per (image,offset): con, dis, hom, asm

// ---------------- reductions ----------------
template <typename T>
__device__ __forceinline__ T warp_sum(T v) {
#pragma unroll
    for (int s = 16; s > 0; s >>= 1) v += __shfl_down_sync(0xffffffffu, v, s);
    return v;
}

template <typename T>
__device__ __forceinline__ T block_sum(T v, T* buf) {
    int lane = threadIdx.x & 31;
    int w    = threadIdx.x >> 5;
    v = warp_sum(v);
    if (lane == 0) buf[w] = v;
    __syncthreads();
    int nw = blockDim.x >> 5;
    T r = (threadIdx.x < nw) ? buf[threadIdx.x] : (T)0;
    if (w == 0) r = warp_sum(r);
    __syncthreads();
    return r;  // valid on thread 0
}

// ---------------- pass 1: gray conversion + std ----------------
// x: (B=16, C=3, F=16, H=224, W=224) float32. n = b*16+f. One CTA per image.
// NPIX = 50176 = 12544 * 4 -> float4 vectorized.
__global__ void __launch_bounds__(256) pass1_gray_std(const float* __restrict__ x) {
    __shared__ double rbuf[16];

    int n = blockIdx.x;
    int b = n >> 4, f = n & 15;
    size_t base = ((size_t)(b * 3) * 16 + f) * NPIX;
    const float4* p0 = (const float4*)(x + base);
    const float4* p1 = (const float4*)(x + base + (size_t)16 * NPIX);  // channel stride F*H*W
    const float4* p2 = (const float4*)(x + base + (size_t)32 * NPIX);
    uchar4* g4 = (uchar4*)(d_g + (size_t)n * NPIX);

    double s1 = 0.0, s2 = 0.0;
    const int NV = NPIX / 4;  // 12544
    for (int i = threadIdx.x; i < NV; i += blockDim.x) {
        float4 a = p0[i], bb = p1[i], c = p2[i];
        float g0 = floorf((a.x + bb.x + c.x) * (255.0f / 3.0f) *
                          (3.0f / 3.0f) / 1.0f);  // keep exact op order below instead
        // exact reference order: mean = sum/3 ; g = floor(mean*255)
        g0          = floorf(((a.x + bb.x + c.x) / 3.0f) * 255.0f);
        float g1    = floorf(((a.y + bb.y + c.y) / 3.0f) * 255.0f);
        float g2    = floorf(((a.z + bb.z + c.z) / 3.0f) * 255.0f);
        float g3    = floorf(((a.w + bb.w + c.w) / 3.0f) * 255.0f);
        g4[i] = make_uchar4((unsigned char)(int)g0, (unsigned char)(int)g1,
                            (unsigned char)(int)g2, (unsigned char)(int)g3);
        s1 += (double)g0 + (double)g1 + (double)g2 + (double)g3;
        s2 += (double)g0 * g0 + (double)g1 * g1 + (double)g2 * g2 + (double)g3 * g3;
    }
    double t1 = block_sum<double>(s1, rbuf);
    double t2 = block_sum<double>(s2, rbuf);
    if (threadIdx.x == 0) {
        double mean = t1 / (double)NPIX;
        double var  = t2 / (double)NPIX - mean * mean;
        if (var < 0.0) var = 0.0;
        d_std[n] = (float)sqrt(var);
    }
}

// ---------------- pass 2: GLCM per (image, offset) ----------------
// 128 KB dynamic shared histogram: 65536 uint16 bins packed 2-per-uint32.
// Max bin count <= 49952 < 65536, so packed halves never carry into each other.
__global__ void __launch_bounds__(512) pass2_glcm() {
    extern __shared__ unsigned int hist[];   // 32768 words = 65536 uint16 bins
    __shared__ float lut[256];               // homogeneity weights 1/(1+d^2)
    __shared__ unsigned int rbuf_u[16];
    __shared__ float rbuf_f[16];
    __shared__ unsigned long long rbuf_ull[16];

    int n = blockIdx.x >> 2;
    int o = blockIdx.x & 3;

    // OFFSETS = [(0,1),(1,1),(1,0),(1,-1)]
    // pair: a = g[r, c + ca], b = g[r+dr, c + cb]; r in [0,nr), c in [0,nc)
    const int drA[4] = {0, 1, 1, 1};
    const int caA[4] = {0, 0, 0, 1};
    const int cbA[4] = {1, 1, 0, 0};
    const int nrA[4] = {224, 223, 223, 223};
    const int ncA[4] = {223, 223, 224, 223};
    int dr = drA[o], ca = caA[o], cb = cbA[o], nr = nrA[o], nc = ncA[o];

    const unsigned char* __restrict__ g = d_g + (size_t)n * NPIX;

    // init shared
    for (int i = threadIdx.x; i < 32768; i += blockDim.x) hist[i] = 0u;
    for (int i = threadIdx.x; i < 256; i += blockDim.x)
        lut[i] = 1.0f / (1.0f + (float)(i * i));
    __syncthreads();

    // histogram + direct-sum features
    unsigned int sd2 = 0, sad = 0;
    float shom = 0.0f;
    int total = nr * nc;
    for (int idx = threadIdx.x; idx < total; idx += blockDim.x) {
        int r = idx / nc;
        int c = idx - r * nc;
        int av = __ldg(&g[r * WW + c + ca]);
        int bv = __ldg(&g[(r + dr) * WW + c + cb]);
        int k = (av << 8) | bv;
        atomicAdd(&hist[k >> 1], 1u << ((k & 1) << 4));
        int d = av - bv;
        unsigned int ad = (unsigned int)(d < 0 ? -d : d);
        sd2 += ad * ad;
        sad += ad;
        shom += lut[ad];
    }
    __syncthreads();

    // ASM: sum over all (i,j) of (H[i,j] + H[j,i])^2
    const unsigned short* h16 = (const unsigned short*)hist;
    unsigned long long sasm = 0ull;
    for (int k = threadIdx.x; k < 65536; k += blockDim.x) {
        int i = k >> 8, j = k & 255;
        unsigned int v = (unsigned int)h16[k] + (unsigned int)h16[(j << 8) | i];
        sasm += (unsigned long long)v * (unsigned long long)v;
    }

    unsigned int t_d2  = block_sum<unsigned int>(sd2, rbuf_u);
    unsigned int t_ad  = block_sum<unsigned int>(sad, rbuf_u);
    float        t_hom = block_sum<float>(shom, rbuf_f);
    unsigned long long t_asm = block_sum<unsigned long long>(sasm, rbuf_ull);

    if (threadIdx.x == 0) {
        double C = (double)total;
        float* out = &d_feat[(size_t)blockIdx.x * 4];
        out[0] = (float)((double)t_d2 / C);                 // contrast
        out[1] = (float)((double)t_ad / C);                 // dissimilarity
        out[2] = (float)((double)t_hom / C);                // homogeneity
        out[3] = (float)((double)t_asm / (4.0 * C * C));    // ASM
    }
}

// ---------------- pass 3: average offsets, write output ----------------
__global__ void __launch_bounds__(256) pass3_finalize(float* __restrict__ out) {
    int n = threadIdx.x;   // 256 threads = NIMG
    float con = 0.f, dis = 0.f, hom = 0.f, as = 0.f;
#pragma unroll
    for (int o = 0; o < 4; o++) {
        const float* fp = &d_feat[(size_t)(n * 4 + o) * 4];
        con += fp[0]; dis += fp[1]; hom += fp[2]; as += fp[3];
    }
    con *= 0.25f; dis *= 0.25f; hom *= 0.25f; as *= 0.25f;
    // output (B, F*6): flat index n*6 + k  (n = b*16+f)
    out[n * 6 + 0] = d_std[n];
    out[n * 6 + 1] = con;
    out[n * 6 + 2] = dis;
    out[n * 6 + 3] = hom;
    out[n * 6 + 4] = as;
    out[n * 6 + 5] = sqrtf(as);
}

extern "C" void kernel_launch(void* const* d_in, const int* in_sizes, int n_in,
                              void* d_out, int out_size) {
    (void)in_sizes; (void)n_in; (void)out_size;
    cudaFuncSetAttribute(pass2_glcm, cudaFuncAttributeMaxDynamicSharedMemorySize, 131072);
    const float* x = (const float*)d_in[0];
    float* out = (float*)d_out;
    pass1_gray_std<<<NIMG, 256>>>(x);
    pass2_glcm<<<NIMG * NOFF, 512, 131072>>>();
    pass3_finalize<<<1, 256>>>(out);
}